// round 6
// baseline (speedup 1.0000x reference)
#include <cuda_runtime.h>
#include <cuda_bf16.h>
#include <math.h>

// ControlNorm2D: B=32, C=256, H=64, W=64
// out[b,c,h,w] = (x[b,c,h,w] - mu_stale[b,c]) / sqrt(var_stale[b,c] + eps)
//
// R6 = R5 resubmitted (broker timeout, never measured):
// minimize per-thread batched-load count (MLP_p1=1) per the measured
// regression of R4 (8 loads/thread made stats WORSE). 1024-thread blocks,
// exactly one float4 per thread, one (b,c) slice per block for both memory
// kernels. Norm keeps reverse-order L2 chase + __ldcs/__stcs streaming.

#define B_ 32
#define C_ 256
#define HW_ 4096          // 64*64
#define BC_ (B_ * C_)     // 8192

static __device__ float g_mu[BC_];    // per-(b,c) spatial mean
static __device__ float g_v[BC_];     // per-(b,c) spatial variance
static __device__ float g_mub[BC_];   // stale EMA mean (_mu_b)
static __device__ float g_inv[BC_];   // 1/sqrt(_var_b + eps)

// ---------------------------------------------------------------------------
// Kernel 1: per-(b,c) mean and E[x^2]. One block per slice, 1024 threads,
// exactly ONE float4 load per thread (MLP_p1 = 1).
// ---------------------------------------------------------------------------
__global__ __launch_bounds__(1024) void stats_kernel(const float* __restrict__ x) {
    const int bc  = blockIdx.x;
    const int tid = threadIdx.x;
    const float4* xp = reinterpret_cast<const float4*>(x) + (size_t)bc * (HW_ / 4);

    float4 v = xp[tid];                 // single load in flight per thread
    float s  = (v.x + v.y) + (v.z + v.w);
    float ss = v.x * v.x + v.y * v.y + v.z * v.z + v.w * v.w;

    // warp reduce
#pragma unroll
    for (int o = 16; o > 0; o >>= 1) {
        s  += __shfl_down_sync(0xffffffffu, s,  o);
        ss += __shfl_down_sync(0xffffffffu, ss, o);
    }

    __shared__ float sh_s[32], sh_ss[32];
    const int w = tid >> 5, l = tid & 31;
    if (l == 0) { sh_s[w] = s; sh_ss[w] = ss; }
    __syncthreads();

    if (w == 0) {
        s  = sh_s[l];
        ss = sh_ss[l];
#pragma unroll
        for (int o = 16; o > 0; o >>= 1) {
            s  += __shfl_down_sync(0xffffffffu, s,  o);
            ss += __shfl_down_sync(0xffffffffu, ss, o);
        }
        if (l == 0) {
            const float inv_n = 1.f / (float)HW_;
            float mu = s * inv_n;
            g_mu[bc] = mu;
            g_v[bc]  = ss * inv_n - mu * mu;
        }
    }
}

// ---------------------------------------------------------------------------
// Kernel 2: lin_momentum x2 per channel, one thread per channel, window sums
// as direct 32-wide dot products (mirrors the reference einsum exactly).
// ---------------------------------------------------------------------------
__global__ __launch_bounds__(256) void recur_kernel(
    const float* __restrict__ m,
    const float* __restrict__ var,
    const float* __restrict__ m_p,
    const float* __restrict__ var_p)
{
    const int c = threadIdx.x;
    const float AF   = 0.999f;
    const float OMA  = (float)(1.0 - 0.999);      // matches ref (double->f32)
    const float AFB  = (float)(0.999 * 0.999 * 0.999 * 0.999 * 0.999 * 0.999 * 0.999 * 0.999 *
                               0.999 * 0.999 * 0.999 * 0.999 * 0.999 * 0.999 * 0.999 * 0.999 *
                               0.999 * 0.999 * 0.999 * 0.999 * 0.999 * 0.999 * 0.999 * 0.999 *
                               0.999 * 0.999 * 0.999 * 0.999 * 0.999 * 0.999 * 0.999 * 0.999);
    const float EPSV = 1e-5f;

    float pw[B_];                      // pw[j] = AF^(31-j)
    pw[B_ - 1] = 1.f;
#pragma unroll
    for (int j = B_ - 2; j >= 0; --j) pw[j] = pw[j + 1] * AF;

    // ---------- phase A: mean EMA ----------
    float seq1[2 * B_ - 1];
#pragma unroll
    for (int k = 0; k < B_ - 1; ++k) seq1[k] = m_p[(k + 1) * C_ + c];
#pragma unroll
    for (int k = 0; k < B_; ++k)     seq1[B_ - 1 + k] = g_mu[k * C_ + c];

    float seq2[2 * B_ - 1];
#pragma unroll
    for (int k = 0; k < B_ - 1; ++k) seq2[k] = var_p[(k + 1) * C_ + c];

    float prev_new = 0.f;
    const float m_last = m[(B_ - 1) * C_ + c];
#pragma unroll
    for (int i = 0; i < B_; ++i) {
        float tmp = 0.f;
#pragma unroll
        for (int j = 0; j < B_; ++j) tmp += pw[j] * seq1[i + j];

        float nw    = AFB * m[i * C_ + c] + OMA * tmp;
        float stale = (i == 0) ? m_last : prev_new;
        prev_new    = nw;
        g_mub[i * C_ + c] = stale;

        float d = seq1[B_ - 1 + i] - stale;
        seq2[B_ - 1 + i] = g_v[i * C_ + c] + AF * d * d;
    }

    // ---------- phase B: var EMA ----------
    prev_new = 0.f;
    const float var_last = var[(B_ - 1) * C_ + c];
#pragma unroll
    for (int i = 0; i < B_; ++i) {
        float tmp = 0.f;
#pragma unroll
        for (int j = 0; j < B_; ++j) tmp += pw[j] * seq2[i + j];

        float nw    = AFB * var[i * C_ + c] + OMA * tmp;
        float stale = (i == 0) ? var_last : prev_new;
        prev_new    = nw;
        g_inv[i * C_ + c] = 1.f / sqrtf(stale + EPSV);
    }
}

// ---------------------------------------------------------------------------
// Kernel 3: normalize. One block per slice (REVERSE order to chase stats'
// L2-resident tail of x), 1024 threads, one __ldcs + one __stcs per thread.
// ---------------------------------------------------------------------------
__global__ __launch_bounds__(1024) void norm_kernel(const float* __restrict__ x,
                                                    float* __restrict__ out) {
    const int bc  = (BC_ - 1) - blockIdx.x;     // reverse order
    const int tid = threadIdx.x;
    const float mu  = g_mub[bc];
    const float inv = g_inv[bc];

    const float4* xp = reinterpret_cast<const float4*>(x) + (size_t)bc * (HW_ / 4);
    float4*       op = reinterpret_cast<float4*>(out)     + (size_t)bc * (HW_ / 4);

    float4 v = __ldcs(&xp[tid]);        // last use of x: evict-first read
    v.x = (v.x - mu) * inv;
    v.y = (v.y - mu) * inv;
    v.z = (v.z - mu) * inv;
    v.w = (v.w - mu) * inv;
    __stcs(&op[tid], v);                // streaming store: don't evict x in L2
}

// ---------------------------------------------------------------------------
extern "C" void kernel_launch(void* const* d_in, const int* in_sizes, int n_in,
                              void* d_out, int out_size) {
    const float* x     = (const float*)d_in[0];
    const float* m     = (const float*)d_in[1];
    const float* var   = (const float*)d_in[2];
    const float* m_p   = (const float*)d_in[3];
    const float* var_p = (const float*)d_in[4];
    float* out = (float*)d_out;

    stats_kernel<<<BC_, 1024>>>(x);
    recur_kernel<<<1, C_>>>(m, var, m_p, var_p);
    norm_kernel<<<BC_, 1024>>>(x, out);
}

// round 16
// speedup vs baseline: 1.5020x; 1.5020x over previous
#include <cuda_runtime.h>
#include <cuda_bf16.h>
#include <math.h>

// ControlNorm2D: B=32, C=256, H=64, W=64
//
// R16 = R8 resubmitted unchanged (repeated broker timeouts; never measured):
//  - stats: exact R2 config (4 float4/thread, 256 thr, 1 slice/block) = 23.9us
//  - recur: split into 2 grid-32 kernels (phase A / phase B), block i computes
//           window i-1 redundantly -> no cross-block dependency
//  - norm:  4 __ldcs float4/thread, 256 thr, 1 slice/block, REVERSE bc order
//           (chase stats' L2-resident tail), __stcs stores

#define B_ 32
#define C_ 256
#define HW_ 4096
#define BC_ (B_ * C_)

#define AF_F   0.999f
#define OMA_F  ((float)(1.0 - 0.999))
#define AFB_F  ((float)(0.999 * 0.999 * 0.999 * 0.999 * 0.999 * 0.999 * 0.999 * 0.999 * \
                        0.999 * 0.999 * 0.999 * 0.999 * 0.999 * 0.999 * 0.999 * 0.999 * \
                        0.999 * 0.999 * 0.999 * 0.999 * 0.999 * 0.999 * 0.999 * 0.999 * \
                        0.999 * 0.999 * 0.999 * 0.999 * 0.999 * 0.999 * 0.999 * 0.999))
#define EPS_F  1e-5f

static __device__ float g_mu[BC_];     // per-(b,c) spatial mean
static __device__ float g_v[BC_];      // per-(b,c) spatial variance
static __device__ float g_varc[BC_];   // var_current
static __device__ float g_mub[BC_];    // stale EMA mean (_mu_b)
static __device__ float g_inv[BC_];    // 1/sqrt(_var_b + eps)

// ---------------------------------------------------------------------------
// Kernel 1: per-(b,c) mean and E[x^2]. One block per slice, 256 threads,
// 4 float4 loads per thread (measured-optimal config from R2).
// ---------------------------------------------------------------------------
__global__ __launch_bounds__(256) void stats_kernel(const float* __restrict__ x) {
    const int bc  = blockIdx.x;
    const int tid = threadIdx.x;
    const float4* xp = reinterpret_cast<const float4*>(x) + (size_t)bc * (HW_ / 4);

    float s = 0.f, ss = 0.f;
#pragma unroll
    for (int i = 0; i < 4; ++i) {
        float4 v = xp[i * 256 + tid];
        s  += (v.x + v.y) + (v.z + v.w);
        ss += v.x * v.x + v.y * v.y + v.z * v.z + v.w * v.w;
    }

#pragma unroll
    for (int o = 16; o > 0; o >>= 1) {
        s  += __shfl_down_sync(0xffffffffu, s,  o);
        ss += __shfl_down_sync(0xffffffffu, ss, o);
    }

    __shared__ float sh_s[8], sh_ss[8];
    const int w = tid >> 5, l = tid & 31;
    if (l == 0) { sh_s[w] = s; sh_ss[w] = ss; }
    __syncthreads();

    if (w == 0) {
        s  = (l < 8) ? sh_s[l]  : 0.f;
        ss = (l < 8) ? sh_ss[l] : 0.f;
#pragma unroll
        for (int o = 4; o > 0; o >>= 1) {
            s  += __shfl_down_sync(0xffffffffu, s,  o);
            ss += __shfl_down_sync(0xffffffffu, ss, o);
        }
        if (l == 0) {
            const float inv_n = 1.f / (float)HW_;
            float mu = s * inv_n;
            g_mu[bc] = mu;
            g_v[bc]  = ss * inv_n - mu * mu;
        }
    }
}

// ---------------------------------------------------------------------------
// Recurrence phase A (mean EMA). Grid = B_ blocks, 256 threads (one channel
// each). Block i computes window dot i-1 -> stale = new[i-1], then
// g_mub[i,c] and var_current[i,c]. seq1(idx) = idx<31 ? m_p[idx+1] : mu[idx-31]
// ---------------------------------------------------------------------------
__global__ __launch_bounds__(256) void recurA_kernel(
    const float* __restrict__ m,
    const float* __restrict__ m_p)
{
    const int i = blockIdx.x;
    const int c = threadIdx.x;

    float pw[B_];                      // pw[j] = AF^(31-j)
    pw[B_ - 1] = 1.f;
#pragma unroll
    for (int j = B_ - 2; j >= 0; --j) pw[j] = pw[j + 1] * AF_F;

    float stale;
    if (i == 0) {
        stale = m[(B_ - 1) * C_ + c];
    } else {
        float tmp_im1 = 0.f;
#pragma unroll
        for (int j = 0; j < B_; ++j) {
            int idx = i - 1 + j;
            float v = (idx < B_ - 1) ? m_p[(idx + 1) * C_ + c]
                                     : g_mu[(idx - (B_ - 1)) * C_ + c];
            tmp_im1 += pw[j] * v;
        }
        stale = AFB_F * m[(i - 1) * C_ + c] + OMA_F * tmp_im1;   // new[i-1]
    }

    g_mub[i * C_ + c] = stale;
    float d = g_mu[i * C_ + c] - stale;
    g_varc[i * C_ + c] = g_v[i * C_ + c] + AF_F * d * d;
}

// ---------------------------------------------------------------------------
// Recurrence phase B (var EMA). Grid = B_ blocks. Block i needs window i-1
// only (stale2[i] = new2[i-1]); i==0 uses var[31,c] directly.
// seq2(idx) = idx<31 ? var_p[idx+1] : var_current[idx-31]
// ---------------------------------------------------------------------------
__global__ __launch_bounds__(256) void recurB_kernel(
    const float* __restrict__ var,
    const float* __restrict__ var_p)
{
    const int i = blockIdx.x;
    const int c = threadIdx.x;

    float pw[B_];
    pw[B_ - 1] = 1.f;
#pragma unroll
    for (int j = B_ - 2; j >= 0; --j) pw[j] = pw[j + 1] * AF_F;

    float stale;
    if (i == 0) {
        stale = var[(B_ - 1) * C_ + c];
    } else {
        float tmp_im1 = 0.f;
#pragma unroll
        for (int j = 0; j < B_; ++j) {
            int idx = i - 1 + j;
            float v = (idx < B_ - 1) ? var_p[(idx + 1) * C_ + c]
                                     : g_varc[(idx - (B_ - 1)) * C_ + c];
            tmp_im1 += pw[j] * v;
        }
        stale = AFB_F * var[(i - 1) * C_ + c] + OMA_F * tmp_im1;  // new2[i-1]
    }

    g_inv[i * C_ + c] = 1.f / sqrtf(stale + EPS_F);
}

// ---------------------------------------------------------------------------
// Kernel 4: normalize. One block per slice, 256 threads, 4 float4 per thread,
// REVERSE bc order; __ldcs reads (last use), __stcs stores (protect x in L2).
// ---------------------------------------------------------------------------
__global__ __launch_bounds__(256) void norm_kernel(const float* __restrict__ x,
                                                   float* __restrict__ out) {
    const int bc  = (BC_ - 1) - blockIdx.x;
    const int tid = threadIdx.x;
    const float mu  = g_mub[bc];
    const float inv = g_inv[bc];

    const float4* xp = reinterpret_cast<const float4*>(x) + (size_t)bc * (HW_ / 4);
    float4*       op = reinterpret_cast<float4*>(out)     + (size_t)bc * (HW_ / 4);

    float4 r[4];
#pragma unroll
    for (int i = 0; i < 4; ++i) r[i] = __ldcs(&xp[i * 256 + tid]);

#pragma unroll
    for (int i = 0; i < 4; ++i) {
        float4 v = r[i];
        v.x = (v.x - mu) * inv;
        v.y = (v.y - mu) * inv;
        v.z = (v.z - mu) * inv;
        v.w = (v.w - mu) * inv;
        __stcs(&op[i * 256 + tid], v);
    }
}

// ---------------------------------------------------------------------------
extern "C" void kernel_launch(void* const* d_in, const int* in_sizes, int n_in,
                              void* d_out, int out_size) {
    const float* x     = (const float*)d_in[0];
    const float* m     = (const float*)d_in[1];
    const float* var   = (const float*)d_in[2];
    const float* m_p   = (const float*)d_in[3];
    const float* var_p = (const float*)d_in[4];
    float* out = (float*)d_out;

    stats_kernel<<<BC_, 256>>>(x);
    recurA_kernel<<<B_, C_>>>(m, m_p);
    recurB_kernel<<<B_, C_>>>(var, var_p);
    norm_kernel<<<BC_, 256>>>(x, out);
}